// round 1
// baseline (speedup 1.0000x reference)
#include <cuda_runtime.h>
#include <cstdint>

// Problem constants (fixed shapes from reference)
#define BB   8
#define CC   256
#define HH   64
#define WWD  64
#define OO   256
#define KKT  9
#define HWSZ 4096            // HH*WWD
#define CK   (CC*KKT)        // 2304

#define TO   128             // o-tile
#define TP   128             // pixel tile
#define NT   256             // threads per block

// Pre-transposed weight: g_wt[(c*9+k)*256 + o]
__device__ float g_wt[CK * OO];

__global__ void transpose_weight_kernel(const float* __restrict__ w) {
    int ck = blockIdx.x;            // 0..2303
    int o  = threadIdx.x;           // 0..255
    g_wt[ck * OO + o] = w[o * CK + ck];
}

__global__ __launch_bounds__(NT, 2)
void dcn_fused_kernel(const float* __restrict__ inp,
                      const float* __restrict__ offs,
                      const float* __restrict__ mask,
                      const float* __restrict__ bias,
                      float* __restrict__ out) {
    // Sampling precompute (per-block, channel-independent):
    __shared__ uint16_t sI[4][KKT * TP];   // clamped corner indices into 64x64 plane
    __shared__ float    sW[4][KKT * TP];   // bilinear weights * mask (0 if invalid)
    __shared__ float    As[KKT * TO];      // weight tile for current channel
    __shared__ float    Bs[KKT * TP];      // column tile for current channel

    const int b   = blockIdx.z;
    const int o0  = blockIdx.y * TO;
    const int hw0 = blockIdx.x * TP;
    const int tid = threadIdx.x;

    // ---- Phase 1: precompute bilinear taps for 9 kernel positions x 128 pixels ----
    for (int i = tid; i < KKT * TP; i += NT) {
        const int k  = i / TP;
        const int p  = i - k * TP;
        const int hw = hw0 + p;
        const int h  = hw >> 6;
        const int w  = hw & 63;

        const float oy = offs[((size_t)b * 18 + k * 2 + 0) * HWSZ + hw];
        const float ox = offs[((size_t)b * 18 + k * 2 + 1) * HWSZ + hw];
        const float m  = mask[((size_t)b * KKT + k) * HWSZ + hw];

        const float py = (float)(h - 1 + k / 3) + oy;
        const float px = (float)(w - 1 + k % 3) + ox;

        const float fy = floorf(py);
        const float fx = floorf(px);
        const int y0 = (int)fy;
        const int x0 = (int)fx;
        const float ly = py - fy, lx = px - fx;
        const float hy = 1.0f - ly, hx = 1.0f - lx;

        const bool vy0 = (y0 >= 0) && (y0 < HH);
        const bool vy1 = (y0 + 1 >= 0) && (y0 + 1 < HH);
        const bool vx0 = (x0 >= 0) && (x0 < WWD);
        const bool vx1 = (x0 + 1 >= 0) && (x0 + 1 < WWD);

        const int cy0 = min(max(y0, 0), HH - 1);
        const int cy1 = min(max(y0 + 1, 0), HH - 1);
        const int cx0 = min(max(x0, 0), WWD - 1);
        const int cx1 = min(max(x0 + 1, 0), WWD - 1);

        sI[0][i] = (uint16_t)(cy0 * WWD + cx0);
        sI[1][i] = (uint16_t)(cy0 * WWD + cx1);
        sI[2][i] = (uint16_t)(cy1 * WWD + cx0);
        sI[3][i] = (uint16_t)(cy1 * WWD + cx1);

        sW[0][i] = (vy0 && vx0) ? hy * hx * m : 0.0f;
        sW[1][i] = (vy0 && vx1) ? hy * lx * m : 0.0f;
        sW[2][i] = (vy1 && vx0) ? ly * hx * m : 0.0f;
        sW[3][i] = (vy1 && vx1) ? ly * lx * m : 0.0f;
    }

    // ---- Phase 2: GEMM over channels with on-the-fly column construction ----
    float acc[8][8];
    #pragma unroll
    for (int io = 0; io < 8; ++io)
        #pragma unroll
        for (int ip = 0; ip < 8; ++ip)
            acc[io][ip] = 0.0f;

    const int ty = tid >> 4;     // 0..15 -> o micro-row
    const int tx = tid & 15;     // 0..15 -> pixel micro-col
    const float* __restrict__ inb = inp + (size_t)b * CC * HWSZ;

    for (int c = 0; c < CC; ++c) {
        __syncthreads();
        // Stage weight tile: As[k*128 + o] = g_wt[(c*9+k)*256 + o0 + o]  (coalesced)
        const float* __restrict__ wsrc = g_wt + (size_t)c * KKT * OO + o0;
        for (int i = tid; i < KKT * TO; i += NT) {
            const int k = i >> 7;
            const int o = i & 127;
            As[i] = wsrc[k * OO + o];
        }
        // Build column tile: 4 gathers per element using precomputed taps
        const float* __restrict__ plane = inb + (size_t)c * HWSZ;
        for (int i = tid; i < KKT * TP; i += NT) {
            float v = sW[0][i] * __ldg(plane + sI[0][i]);
            v      += sW[1][i] * __ldg(plane + sI[1][i]);
            v      += sW[2][i] * __ldg(plane + sI[2][i]);
            v      += sW[3][i] * __ldg(plane + sI[3][i]);
            Bs[i] = v;
        }
        __syncthreads();

        #pragma unroll
        for (int k = 0; k < KKT; ++k) {
            float a[8], bv[8];
            *(float4*)&a[0]  = *(const float4*)&As[k * TO + ty * 8];
            *(float4*)&a[4]  = *(const float4*)&As[k * TO + ty * 8 + 4];
            *(float4*)&bv[0] = *(const float4*)&Bs[k * TP + tx * 8];
            *(float4*)&bv[4] = *(const float4*)&Bs[k * TP + tx * 8 + 4];
            #pragma unroll
            for (int io = 0; io < 8; ++io)
                #pragma unroll
                for (int ip = 0; ip < 8; ++ip)
                    acc[io][ip] += a[io] * bv[ip];
        }
    }

    // ---- Epilogue: add bias, store ----
    #pragma unroll
    for (int io = 0; io < 8; ++io) {
        const int o = o0 + ty * 8 + io;
        const float bvv = bias[o];
        float4 v0, v1;
        v0.x = acc[io][0] + bvv; v0.y = acc[io][1] + bvv;
        v0.z = acc[io][2] + bvv; v0.w = acc[io][3] + bvv;
        v1.x = acc[io][4] + bvv; v1.y = acc[io][5] + bvv;
        v1.z = acc[io][6] + bvv; v1.w = acc[io][7] + bvv;
        float* dst = out + ((size_t)b * OO + o) * HWSZ + hw0 + tx * 8;
        *(float4*)dst       = v0;
        *(float4*)(dst + 4) = v1;
    }
}

extern "C" void kernel_launch(void* const* d_in, const int* in_sizes, int n_in,
                              void* d_out, int out_size) {
    const float* inp    = (const float*)d_in[0];  // [8,256,64,64]
    const float* offs   = (const float*)d_in[1];  // [8,18,64,64]
    const float* mask   = (const float*)d_in[2];  // [8,9,64,64]
    const float* weight = (const float*)d_in[3];  // [256,256,3,3]
    const float* bias   = (const float*)d_in[4];  // [256]
    float* out = (float*)d_out;                   // [8,256,64,64]

    transpose_weight_kernel<<<CK, OO>>>(weight);

    dim3 grid(HWSZ / TP, OO / TO, BB);            // (32, 2, 8)
    dcn_fused_kernel<<<grid, NT>>>(inp, offs, mask, bias, out);
}

// round 2
// speedup vs baseline: 2.3626x; 2.3626x over previous
#include <cuda_runtime.h>
#include <cuda_bf16.h>
#include <cstdint>

// Fixed problem shape
#define BB   8
#define CC   256
#define HH   64
#define WWD  64
#define OO   256
#define KKT  9
#define HWSZ 4096

#define TP   128      // pixel tile per block
#define NT   512      // threads (16 warps: 4 M-warps x 4 N-warps)

#define AS_STRIDE 40   // bf16 elems per A-tile row (32 + 8 pad) -> 80B, conflict-free ldmatrix
#define BS_STRIDE 136  // bf16 elems per B-tile row (128 + 8 pad) -> 272B, conflict-free ldmatrix

// ---- device scratch (static; no runtime alloc) ----
__device__ __align__(16) __nv_bfloat16 g_whi[KKT * OO * CC];
__device__ __align__(16) __nv_bfloat16 g_wlo[KKT * OO * CC];
__device__ __align__(16) float         g_xn[(size_t)BB * HWSZ * CC];   // NHWC fp32

// ---------------- prep: weight split fp32 -> bf16 hi/lo, layout [k][o][c] ----------------
__global__ void prep_weight(const float* __restrict__ w) {
    int o = blockIdx.x;            // 0..255
    int k = blockIdx.y;            // 0..8
    int c = threadIdx.x;           // 0..255
    float v = w[((size_t)o * CC + c) * KKT + k];
    __nv_bfloat16 hi = __float2bfloat16_rn(v);
    float lo = v - __bfloat162float(hi);
    size_t idx = ((size_t)k * OO + o) * CC + c;
    g_whi[idx] = hi;
    g_wlo[idx] = __float2bfloat16_rn(lo);
}

// ---------------- prep: NCHW -> NHWC (tiled transpose per batch) ----------------
__global__ void prep_nhwc(const float* __restrict__ x) {
    __shared__ float tile[32][33];
    int bb  = blockIdx.z;
    int hw0 = blockIdx.x * 32;
    int c0  = blockIdx.y * 32;
    int tx = threadIdx.x;          // 0..31 (hw within tile on load)
    int ty = threadIdx.y;          // 0..7
    const float* src = x + (size_t)bb * CC * HWSZ;
    #pragma unroll
    for (int i = 0; i < 32; i += 8)
        tile[ty + i][tx] = src[(size_t)(c0 + ty + i) * HWSZ + hw0 + tx];
    __syncthreads();
    float* dst = g_xn + (size_t)bb * HWSZ * CC;
    #pragma unroll
    for (int i = 0; i < 32; i += 8)
        dst[(size_t)(hw0 + ty + i) * CC + c0 + tx] = tile[tx][ty + i];
}

// ---------------- fused DCN: taps -> coalesced gather -> bf16 split -> mma.sync ----------------
struct SmemLayout {
    uint16_t      sI[4][KKT * TP];          // 9216 B
    float         sW[4][KKT * TP];          // 18432 B
    __nv_bfloat16 As[2][OO * AS_STRIDE];    // 40960 B  (hi, lo)
    __nv_bfloat16 Bs[2][32 * BS_STRIDE];    // 17408 B  (hi, lo)
};
#define SMEM_BYTES 86016
static_assert(sizeof(SmemLayout) == SMEM_BYTES, "smem layout size");

__device__ __forceinline__ void ldsm_x4(uint32_t addr, uint32_t& r0, uint32_t& r1,
                                        uint32_t& r2, uint32_t& r3) {
    asm volatile("ldmatrix.sync.aligned.m8n8.x4.shared.b16 {%0,%1,%2,%3}, [%4];"
                 : "=r"(r0), "=r"(r1), "=r"(r2), "=r"(r3) : "r"(addr));
}
__device__ __forceinline__ void ldsm_x2_trans(uint32_t addr, uint32_t& r0, uint32_t& r1) {
    asm volatile("ldmatrix.sync.aligned.m8n8.x2.trans.shared.b16 {%0,%1}, [%2];"
                 : "=r"(r0), "=r"(r1) : "r"(addr));
}
__device__ __forceinline__ void mma_bf16(float* d, const uint32_t* a, const uint32_t* bfr) {
    asm volatile("mma.sync.aligned.m16n8k16.row.col.f32.bf16.bf16.f32 "
                 "{%0,%1,%2,%3}, {%4,%5,%6,%7}, {%8,%9}, {%0,%1,%2,%3};"
                 : "+f"(d[0]), "+f"(d[1]), "+f"(d[2]), "+f"(d[3])
                 : "r"(a[0]), "r"(a[1]), "r"(a[2]), "r"(a[3]), "r"(bfr[0]), "r"(bfr[1]));
}

extern __shared__ char smem_raw[];

__global__ __launch_bounds__(NT, 1)
void dcn_mma_kernel(const float* __restrict__ offs,
                    const float* __restrict__ mask,
                    const float* __restrict__ bias,
                    float* __restrict__ out) {
    SmemLayout& sm = *reinterpret_cast<SmemLayout*>(smem_raw);
    const int bb   = blockIdx.y;
    const int hw0  = blockIdx.x * TP;
    const int tid  = threadIdx.x;
    const int lane = tid & 31;
    const int wid  = tid >> 5;         // 0..15
    const int warpM = wid >> 2;        // 0..3  -> o block of 64
    const int warpN = wid & 3;         // 0..3  -> p block of 32

    // ---- Phase 1: bilinear taps (channel-independent), weights premultiplied by mask ----
    for (int i = tid; i < KKT * TP; i += NT) {
        const int k  = i / TP;
        const int p  = i - k * TP;
        const int hw = hw0 + p;
        const int h  = hw >> 6;
        const int w  = hw & 63;

        const float oy = offs[((size_t)bb * 18 + k * 2 + 0) * HWSZ + hw];
        const float ox = offs[((size_t)bb * 18 + k * 2 + 1) * HWSZ + hw];
        const float m  = mask[((size_t)bb * KKT + k) * HWSZ + hw];

        const float py = (float)(h - 1 + k / 3) + oy;
        const float px = (float)(w - 1 + k % 3) + ox;

        const float fy = floorf(py);
        const float fx = floorf(px);
        const int y0 = (int)fy;
        const int x0 = (int)fx;
        const float ly = py - fy, lx = px - fx;
        const float hy = 1.0f - ly, hx = 1.0f - lx;

        const bool vy0 = (y0 >= 0) && (y0 < HH);
        const bool vy1 = (y0 + 1 >= 0) && (y0 + 1 < HH);
        const bool vx0 = (x0 >= 0) && (x0 < WWD);
        const bool vx1 = (x0 + 1 >= 0) && (x0 + 1 < WWD);

        const int cy0 = min(max(y0, 0), HH - 1);
        const int cy1 = min(max(y0 + 1, 0), HH - 1);
        const int cx0 = min(max(x0, 0), WWD - 1);
        const int cx1 = min(max(x0 + 1, 0), WWD - 1);

        sm.sI[0][i] = (uint16_t)(cy0 * WWD + cx0);
        sm.sI[1][i] = (uint16_t)(cy0 * WWD + cx1);
        sm.sI[2][i] = (uint16_t)(cy1 * WWD + cx0);
        sm.sI[3][i] = (uint16_t)(cy1 * WWD + cx1);

        sm.sW[0][i] = (vy0 && vx0) ? hy * hx * m : 0.0f;
        sm.sW[1][i] = (vy0 && vx1) ? hy * lx * m : 0.0f;
        sm.sW[2][i] = (vy1 && vx0) ? ly * hx * m : 0.0f;
        sm.sW[3][i] = (vy1 && vx1) ? ly * lx * m : 0.0f;
    }
    // (first __syncthreads inside the loop orders taps before first use)

    float acc[4][4][4];
    #pragma unroll
    for (int mf = 0; mf < 4; ++mf)
        #pragma unroll
        for (int nf = 0; nf < 4; ++nf)
            #pragma unroll
            for (int r = 0; r < 4; ++r)
                acc[mf][nf][r] = 0.0f;

    const float* __restrict__ xb = g_xn + (size_t)bb * HWSZ * CC;

    // ---- Phase 2: K loop over (kernel position, channel chunk of 32) ----
    for (int kpos = 0; kpos < KKT; ++kpos) {
        for (int cc8 = 0; cc8 < 8; ++cc8) {
            __syncthreads();
            const int c0 = cc8 * 32;

            // Stage A tile (256 o x 32 c), hi+lo, 16B vector copies
            {
                const int chunk = tid & 3;      // 16B chunk (8 bf16)
                const int row   = tid >> 2;     // 0..127
                #pragma unroll
                for (int pass = 0; pass < 2; ++pass) {
                    const int o = pass * 128 + row;
                    const size_t gidx = ((size_t)kpos * OO + o) * CC + c0 + chunk * 8;
                    *(uint4*)&sm.As[0][o * AS_STRIDE + chunk * 8] = *(const uint4*)(g_whi + gidx);
                    *(uint4*)&sm.As[1][o * AS_STRIDE + chunk * 8] = *(const uint4*)(g_wlo + gidx);
                }
            }

            // Build B tile (32 c x 128 p): coalesced NHWC gathers, lane = channel
            {
                const float* xc = xb + c0 + lane;
                #pragma unroll
                for (int j = 0; j < 8; ++j) {
                    const int pp = wid * 8 + j;
                    const int i  = kpos * TP + pp;
                    float v = sm.sW[0][i] * __ldg(xc + (size_t)sm.sI[0][i] * CC)
                            + sm.sW[1][i] * __ldg(xc + (size_t)sm.sI[1][i] * CC)
                            + sm.sW[2][i] * __ldg(xc + (size_t)sm.sI[2][i] * CC)
                            + sm.sW[3][i] * __ldg(xc + (size_t)sm.sI[3][i] * CC);
                    __nv_bfloat16 hi = __float2bfloat16_rn(v);
                    __nv_bfloat16 lo = __float2bfloat16_rn(v - __bfloat162float(hi));
                    sm.Bs[0][lane * BS_STRIDE + pp] = hi;
                    sm.Bs[1][lane * BS_STRIDE + pp] = lo;
                }
            }
            __syncthreads();

            // MMA: two k16 steps; splits hi*hi + hi*lo + lo*hi
            #pragma unroll
            for (int ks = 0; ks < 2; ++ks) {
                uint32_t a[4][4], bh[4][2], bl[4][2];
                const int arow = warpM * 64 + (lane & 15);
                const int acol = ks * 16 + (lane >> 4) * 8;
                #pragma unroll
                for (int mf = 0; mf < 4; ++mf) {
                    uint32_t addr = (uint32_t)__cvta_generic_to_shared(
                        &sm.As[0][(arow + mf * 16) * AS_STRIDE + acol]);
                    ldsm_x4(addr, a[mf][0], a[mf][1], a[mf][2], a[mf][3]);
                }
                const int brow = ks * 16 + (lane & 15);
                #pragma unroll
                for (int nf = 0; nf < 4; ++nf) {
                    const int bcol = warpN * 32 + nf * 8;
                    uint32_t addrh = (uint32_t)__cvta_generic_to_shared(
                        &sm.Bs[0][brow * BS_STRIDE + bcol]);
                    uint32_t addrl = (uint32_t)__cvta_generic_to_shared(
                        &sm.Bs[1][brow * BS_STRIDE + bcol]);
                    ldsm_x2_trans(addrh, bh[nf][0], bh[nf][1]);
                    ldsm_x2_trans(addrl, bl[nf][0], bl[nf][1]);
                }
                // hi*hi and hi*lo
                #pragma unroll
                for (int mf = 0; mf < 4; ++mf)
                    #pragma unroll
                    for (int nf = 0; nf < 4; ++nf) {
                        mma_bf16(acc[mf][nf], a[mf], bh[nf]);
                        mma_bf16(acc[mf][nf], a[mf], bl[nf]);
                    }
                // reload A as lo, then lo*hi
                #pragma unroll
                for (int mf = 0; mf < 4; ++mf) {
                    uint32_t addr = (uint32_t)__cvta_generic_to_shared(
                        &sm.As[1][(arow + mf * 16) * AS_STRIDE + acol]);
                    ldsm_x4(addr, a[mf][0], a[mf][1], a[mf][2], a[mf][3]);
                }
                #pragma unroll
                for (int mf = 0; mf < 4; ++mf)
                    #pragma unroll
                    for (int nf = 0; nf < 4; ++nf)
                        mma_bf16(acc[mf][nf], a[mf], bh[nf]);
            }
        }
    }

    // ---- Epilogue: bias add + store (fp32) ----
    #pragma unroll
    for (int mf = 0; mf < 4; ++mf) {
        const int o0 = warpM * 64 + mf * 16 + (lane >> 2);
        const float bv0 = bias[o0];
        const float bv1 = bias[o0 + 8];
        #pragma unroll
        for (int nf = 0; nf < 4; ++nf) {
            const int p = hw0 + warpN * 32 + nf * 8 + (lane & 3) * 2;
            float* d0 = out + ((size_t)(bb * OO + o0)) * HWSZ + p;
            float* d1 = out + ((size_t)(bb * OO + o0 + 8)) * HWSZ + p;
            float2 v0, v1;
            v0.x = acc[mf][nf][0] + bv0; v0.y = acc[mf][nf][1] + bv0;
            v1.x = acc[mf][nf][2] + bv1; v1.y = acc[mf][nf][3] + bv1;
            *(float2*)d0 = v0;
            *(float2*)d1 = v1;
        }
    }
}

extern "C" void kernel_launch(void* const* d_in, const int* in_sizes, int n_in,
                              void* d_out, int out_size) {
    const float* inp    = (const float*)d_in[0];  // [8,256,64,64]
    const float* offs   = (const float*)d_in[1];  // [8,18,64,64]
    const float* mask   = (const float*)d_in[2];  // [8,9,64,64]
    const float* weight = (const float*)d_in[3];  // [256,256,3,3]
    const float* bias   = (const float*)d_in[4];  // [256]
    float* out = (float*)d_out;                   // [8,256,64,64]

    cudaFuncSetAttribute(dcn_mma_kernel,
                         cudaFuncAttributeMaxDynamicSharedMemorySize, SMEM_BYTES);

    prep_weight<<<dim3(OO, KKT), CC>>>(weight);
    prep_nhwc<<<dim3(HWSZ / 32, CC / 32, BB), dim3(32, 8)>>>(inp);

    dim3 grid(HWSZ / TP, BB);      // (32, 8)
    dcn_mma_kernel<<<grid, NT, SMEM_BYTES>>>(offs, mask, bias, out);
}

// round 4
// speedup vs baseline: 5.2151x; 2.2074x over previous
#include <cuda_runtime.h>
#include <cuda_fp16.h>
#include <cstdint>

// Fixed problem shape
#define BB   8
#define CC   256
#define HH   64
#define WWD  64
#define OO   256
#define KKT  9
#define HWSZ 4096

#define TP   128         // pixel tile per CTA
#define NT   512         // 16 warps: 4 M-warps (o) x 4 N-warps (px)
#define NITER 36         // 4 c-chunks of 64 x 9 kpos

// ---- smem layout (bytes) ----
#define SM_SI   0          // 4*1152*2  = 9216
#define SM_SW   9216       // 4*1152*4  = 18432 -> 27648
#define SM_A    28672      // 2 bufs x 32768 (256 o x 64 c fp16, SW128) -> 94208
#define SM_B    94208      // 2 bufs x (16384 hi + 16384 lo) (128 px x 64 c fp16) -> 159744
#define SMEM_TOTAL 159744

// ---- device scratch ----
__device__ __align__(16) __half g_wh[KKT * OO * CC];              // [k][o][c] fp16
__device__ __align__(16) float  g_xn[(size_t)BB * HWSZ * CC];     // NHWC fp32

// ---------------- prep kernels ----------------
__global__ void prep_weight(const float* __restrict__ w) {
    int o = blockIdx.x, k = blockIdx.y, c = threadIdx.x;
    float v = w[((size_t)o * CC + c) * KKT + k];
    g_wh[((size_t)k * OO + o) * CC + c] = __float2half_rn(v);
}

__global__ void prep_nhwc(const float* __restrict__ x) {
    __shared__ float tile[32][33];
    int bb = blockIdx.z, hw0 = blockIdx.x * 32, c0 = blockIdx.y * 32;
    int tx = threadIdx.x, ty = threadIdx.y;
    const float* src = x + (size_t)bb * CC * HWSZ;
    #pragma unroll
    for (int i = 0; i < 32; i += 8)
        tile[ty + i][tx] = src[(size_t)(c0 + ty + i) * HWSZ + hw0 + tx];
    __syncthreads();
    float* dst = g_xn + (size_t)bb * HWSZ * CC;
    #pragma unroll
    for (int i = 0; i < 32; i += 8)
        dst[(size_t)(hw0 + ty + i) * CC + c0 + tx] = tile[tx][ty + i];
}

// ---------------- helpers ----------------
__device__ __forceinline__ uint32_t s2u(const void* p) {
    uint32_t r;
    asm("{ .reg .u64 t; cvta.to.shared.u64 t, %1; cvt.u32.u64 %0, t; }" : "=r"(r) : "l"(p));
    return r;
}
__device__ __forceinline__ uint32_t sw128(uint32_t off) {
    return off ^ ((off >> 3) & 0x70);
}
__device__ __forceinline__ void ldsm_x4(uint32_t addr, uint32_t& r0, uint32_t& r1,
                                        uint32_t& r2, uint32_t& r3) {
    asm volatile("ldmatrix.sync.aligned.m8n8.x4.shared.b16 {%0,%1,%2,%3}, [%4];"
                 : "=r"(r0), "=r"(r1), "=r"(r2), "=r"(r3) : "r"(addr));
}
__device__ __forceinline__ void mma_fp16(float* d, const uint32_t* a, uint32_t b0, uint32_t b1) {
    asm volatile("mma.sync.aligned.m16n8k16.row.col.f32.f16.f16.f32 "
                 "{%0,%1,%2,%3}, {%4,%5,%6,%7}, {%8,%9}, {%0,%1,%2,%3};"
                 : "+f"(d[0]), "+f"(d[1]), "+f"(d[2]), "+f"(d[3])
                 : "r"(a[0]), "r"(a[1]), "r"(a[2]), "r"(a[3]), "r"(b0), "r"(b1));
}
__device__ __forceinline__ void cp16(uint32_t dst, const void* src) {
    asm volatile("cp.async.cg.shared.global [%0], [%1], 16;" :: "r"(dst), "l"(src) : "memory");
}
__device__ __forceinline__ void cp_commit() { asm volatile("cp.async.commit_group;" ::: "memory"); }
__device__ __forceinline__ void cp_wait0()  { asm volatile("cp.async.wait_group 0;"  ::: "memory"); }

extern __shared__ char smraw[];

__global__ __launch_bounds__(NT, 1)
void dcn_mma2_kernel(const float* __restrict__ offs,
                     const float* __restrict__ mask,
                     const float* __restrict__ bias,
                     float* __restrict__ out) {
    const int tid  = threadIdx.x;
    const int lane = tid & 31;
    const int wid  = tid >> 5;
    const int warpM = wid >> 2;        // 0..3 -> 64 o-rows
    const int warpN = wid & 3;         // 0..3 -> 32 px
    const int bb   = blockIdx.y;
    const int hw0  = blockIdx.x * TP;

    uint16_t* sI = (uint16_t*)(smraw + SM_SI);
    float*    sW = (float*)(smraw + SM_SW);
    const uint32_t uA  = s2u(smraw + SM_A);
    const uint32_t uBh = s2u(smraw + SM_B);

    // ---- taps: bilinear corner indices + mask-premultiplied weights ----
    for (int i = tid; i < KKT * TP; i += NT) {
        const int k  = i / TP;
        const int p  = i - k * TP;
        const int hw = hw0 + p;
        const int h  = hw >> 6;
        const int w  = hw & 63;

        const float oy = offs[((size_t)bb * 18 + k * 2 + 0) * HWSZ + hw];
        const float ox = offs[((size_t)bb * 18 + k * 2 + 1) * HWSZ + hw];
        const float m  = mask[((size_t)bb * KKT + k) * HWSZ + hw];

        const float py = (float)(h - 1 + k / 3) + oy;
        const float px = (float)(w - 1 + k % 3) + ox;
        const float fy = floorf(py), fx = floorf(px);
        const int y0 = (int)fy, x0 = (int)fx;
        const float ly = py - fy, lx = px - fx;
        const float hy = 1.0f - ly, hx = 1.0f - lx;

        const bool vy0 = (y0 >= 0) && (y0 < HH);
        const bool vy1 = (y0 + 1 >= 0) && (y0 + 1 < HH);
        const bool vx0 = (x0 >= 0) && (x0 < WWD);
        const bool vx1 = (x0 + 1 >= 0) && (x0 + 1 < WWD);
        const int cy0 = min(max(y0, 0), HH - 1);
        const int cy1 = min(max(y0 + 1, 0), HH - 1);
        const int cx0 = min(max(x0, 0), WWD - 1);
        const int cx1 = min(max(x0 + 1, 0), WWD - 1);

        sI[0 * 1152 + i] = (uint16_t)(cy0 * WWD + cx0);
        sI[1 * 1152 + i] = (uint16_t)(cy0 * WWD + cx1);
        sI[2 * 1152 + i] = (uint16_t)(cy1 * WWD + cx0);
        sI[3 * 1152 + i] = (uint16_t)(cy1 * WWD + cx1);
        sW[0 * 1152 + i] = (vy0 && vx0) ? hy * hx * m : 0.0f;
        sW[1 * 1152 + i] = (vy0 && vx1) ? hy * lx * m : 0.0f;
        sW[2 * 1152 + i] = (vy1 && vx0) ? ly * hx * m : 0.0f;
        sW[3 * 1152 + i] = (vy1 && vx1) ? ly * lx * m : 0.0f;
    }
    __syncthreads();

    const float* __restrict__ xb = g_xn + (size_t)bb * HWSZ * CC;

    float acc[4][4][4];
    #pragma unroll
    for (int mf = 0; mf < 4; ++mf)
        #pragma unroll
        for (int nf = 0; nf < 4; ++nf)
            #pragma unroll
            for (int r = 0; r < 4; ++r) acc[mf][nf][r] = 0.0f;

    // --- helper lambdas (inlined) ---
    auto stageA = [&](int jt, int buf) {
        const int kpos = jt % KKT;
        const int c0   = (jt / KKT) * 64;
        const int q = tid & 7;          // 16B chunk within 128B row
        const int r = tid >> 3;         // 0..63
        const uint32_t abase = uA + buf * 32768;
        #pragma unroll
        for (int rr = 0; rr < 4; ++rr) {
            const int row = r + rr * 64;
            const __half* src = g_wh + ((size_t)kpos * OO + row) * CC + c0 + q * 8;
            cp16(abase + sw128((uint32_t)(row * 128 + q * 16)), src);
        }
    };

    float2 g[2][4];           // gather regs for one quarter (2 px x 4 corners)
    auto loadQ = [&](int jt, int q) {
        const int kpos = jt % KKT;
        const int c0   = (jt / KKT) * 64;
        const float* xc = xb + c0 + 2 * lane;
        #pragma unroll
        for (int e = 0; e < 2; ++e) {
            const int i = kpos * TP + wid * 8 + q * 2 + e;
            g[e][0] = *(const float2*)(xc + (size_t)sI[0 * 1152 + i] * CC);
            g[e][1] = *(const float2*)(xc + (size_t)sI[1 * 1152 + i] * CC);
            g[e][2] = *(const float2*)(xc + (size_t)sI[2 * 1152 + i] * CC);
            g[e][3] = *(const float2*)(xc + (size_t)sI[3 * 1152 + i] * CC);
        }
    };
    auto storeQ = [&](int jt, int q, int buf) {
        const int kpos = jt % KKT;
        char* Bhi = smraw + SM_B + buf * 32768;
        char* Blo = Bhi + 16384;
        #pragma unroll
        for (int e = 0; e < 2; ++e) {
            const int pp = wid * 8 + q * 2 + e;
            const int i  = kpos * TP + pp;
            const float w0 = sW[0 * 1152 + i], w1 = sW[1 * 1152 + i];
            const float w2 = sW[2 * 1152 + i], w3 = sW[3 * 1152 + i];
            float2 v;
            v.x = w0 * g[e][0].x + w1 * g[e][1].x + w2 * g[e][2].x + w3 * g[e][3].x;
            v.y = w0 * g[e][0].y + w1 * g[e][1].y + w2 * g[e][2].y + w3 * g[e][3].y;
            __half2 hi2 = __float22half2_rn(v);
            float2 hf = __half22float2(hi2);
            __half2 lo2 = __float22half2_rn(make_float2(v.x - hf.x, v.y - hf.y));
            const uint32_t sw = sw128((uint32_t)(pp * 128 + lane * 4));
            *(uint32_t*)(Bhi + sw) = *(uint32_t*)&hi2;
            *(uint32_t*)(Blo + sw) = *(uint32_t*)&lo2;
        }
    };
    auto mmaKS = [&](int ks, int buf) {
        const uint32_t abase = uA + buf * 32768;
        const uint32_t bbase = uBh + buf * 32768;
        uint32_t a[4][4];
        #pragma unroll
        for (int mf = 0; mf < 4; ++mf) {
            const uint32_t off = (uint32_t)((warpM * 64 + mf * 16 + (lane & 15)) * 128
                                            + ks * 32 + (lane >> 4) * 16);
            ldsm_x4(abase + sw128(off), a[mf][0], a[mf][1], a[mf][2], a[mf][3]);
        }
        uint32_t bh[4][2], bl[4][2];
        #pragma unroll
        for (int pb = 0; pb < 2; ++pb) {
            const uint32_t off = (uint32_t)((warpN * 32 + pb * 16 + (lane & 15)) * 128
                                            + ks * 32 + (lane >> 4) * 16);
            uint32_t r0, r1, r2, r3;
            ldsm_x4(bbase + sw128(off), r0, r1, r2, r3);
            bh[pb * 2 + 0][0] = r0; bh[pb * 2 + 0][1] = r2;
            bh[pb * 2 + 1][0] = r1; bh[pb * 2 + 1][1] = r3;
            ldsm_x4(bbase + 16384 + sw128(off), r0, r1, r2, r3);
            bl[pb * 2 + 0][0] = r0; bl[pb * 2 + 0][1] = r2;
            bl[pb * 2 + 1][0] = r1; bl[pb * 2 + 1][1] = r3;
        }
        #pragma unroll
        for (int mf = 0; mf < 4; ++mf)
            #pragma unroll
            for (int nf = 0; nf < 4; ++nf) {
                mma_fp16(acc[mf][nf], a[mf], bh[nf][0], bh[nf][1]);
                mma_fp16(acc[mf][nf], a[mf], bl[nf][0], bl[nf][1]);
            }
    };

    // ---- prologue: build iteration 0 into buffer 0 ----
    stageA(0, 0);
    cp_commit();
    #pragma unroll
    for (int q = 0; q < 4; ++q) { loadQ(0, q); storeQ(0, q, 0); }
    cp_wait0();
    __syncthreads();

    // ---- main loop: one sync per iter; build(it+1) interleaved with MMA(it) ----
    for (int it = 0; it < NITER; ++it) {
        const int buf = it & 1;
        const bool more = (it + 1 < NITER);
        if (more) { stageA(it + 1, buf ^ 1); cp_commit(); }

        if (more) loadQ(it + 1, 0);
        mmaKS(0, buf);
        if (more) { storeQ(it + 1, 0, buf ^ 1); loadQ(it + 1, 1); }
        mmaKS(1, buf);
        if (more) { storeQ(it + 1, 1, buf ^ 1); loadQ(it + 1, 2); }
        mmaKS(2, buf);
        if (more) { storeQ(it + 1, 2, buf ^ 1); loadQ(it + 1, 3); }
        mmaKS(3, buf);
        if (more) storeQ(it + 1, 3, buf ^ 1);

        cp_wait0();
        __syncthreads();
    }

    // ---- epilogue: bias add + fp32 stores ----
    #pragma unroll
    for (int mf = 0; mf < 4; ++mf) {
        const int o0 = warpM * 64 + mf * 16 + (lane >> 2);
        const float bv0 = bias[o0];
        const float bv1 = bias[o0 + 8];
        #pragma unroll
        for (int nf = 0; nf < 4; ++nf) {
            const int p = hw0 + warpN * 32 + nf * 8 + (lane & 3) * 2;
            float* d0 = out + ((size_t)(bb * OO + o0)) * HWSZ + p;
            float* d1 = out + ((size_t)(bb * OO + o0 + 8)) * HWSZ + p;
            float2 v0, v1;
            v0.x = acc[mf][nf][0] + bv0; v0.y = acc[mf][nf][1] + bv0;
            v1.x = acc[mf][nf][2] + bv1; v1.y = acc[mf][nf][3] + bv1;
            *(float2*)d0 = v0;
            *(float2*)d1 = v1;
        }
    }
}

extern "C" void kernel_launch(void* const* d_in, const int* in_sizes, int n_in,
                              void* d_out, int out_size) {
    const float* inp    = (const float*)d_in[0];  // [8,256,64,64]
    const float* offs   = (const float*)d_in[1];  // [8,18,64,64]
    const float* mask   = (const float*)d_in[2];  // [8,9,64,64]
    const float* weight = (const float*)d_in[3];  // [256,256,3,3]
    const float* bias   = (const float*)d_in[4];  // [256]
    float* out = (float*)d_out;                   // [8,256,64,64]

    cudaFuncSetAttribute(dcn_mma2_kernel,
                         cudaFuncAttributeMaxDynamicSharedMemorySize, SMEM_TOTAL);

    prep_weight<<<dim3(OO, KKT), CC>>>(weight);
    prep_nhwc<<<dim3(HWSZ / 32, CC / 32, BB), dim3(32, 8)>>>(inp);

    dim3 grid(HWSZ / TP, BB);   // (32, 8) = 256 CTAs
    dcn_mma2_kernel<<<grid, NT, SMEM_TOTAL>>>(offs, mask, bias, out);
}

// round 5
// speedup vs baseline: 6.7614x; 1.2965x over previous
#include <cuda_runtime.h>
#include <cuda_fp16.h>
#include <cstdint>

// Fixed problem shape
#define BB   8
#define CC   256
#define HH   64
#define WWD  64
#define OO   256
#define KKT  9
#define HWSZ 4096

#define TP   128         // pixel tile per CTA
#define NT   512         // 16 warps: 4 M-warps (o) x 4 N-warps (px)
#define NITER 18         // 2 c-chunks of 128 x 9 kpos

// ---- smem layout (bytes) ----
// taps: sI 9216 + sW 18432 = 27648
// A: 2 bufs x 65536 (each: 2 half-planes of 32768; 256 o x 64 c fp16, SW128 rows of 128B)
// B: 2 bufs x 32768 (each: 2 half-planes of 16384; 128 px x 64 c fp16, SW128)
#define SM_SI   0
#define SM_SW   9216
#define SM_A    27648
#define SM_B    158720
#define SM_STAGE 27648      // epilogue overlay (128*129*4 = 66048)
#define SMEM_TOTAL 224256

// ---- device scratch ----
__device__ __align__(16) __half g_wh[KKT * OO * CC];              // [k][o][c] fp16
__device__ __align__(16) float  g_xn[(size_t)BB * HWSZ * CC];     // NHWC fp32

// ---------------- prep kernels ----------------
__global__ void prep_weight(const float* __restrict__ w) {
    int o = blockIdx.x, k = blockIdx.y, c = threadIdx.x;
    float v = w[((size_t)o * CC + c) * KKT + k];
    g_wh[((size_t)k * OO + o) * CC + c] = __float2half_rn(v);
}

__global__ void prep_nhwc(const float* __restrict__ x) {
    __shared__ float tile[32][33];
    int bb = blockIdx.z, hw0 = blockIdx.x * 32, c0 = blockIdx.y * 32;
    int tx = threadIdx.x, ty = threadIdx.y;
    const float* src = x + (size_t)bb * CC * HWSZ;
    #pragma unroll
    for (int i = 0; i < 32; i += 8)
        tile[ty + i][tx] = src[(size_t)(c0 + ty + i) * HWSZ + hw0 + tx];
    __syncthreads();
    float* dst = g_xn + (size_t)bb * HWSZ * CC;
    #pragma unroll
    for (int i = 0; i < 32; i += 8)
        dst[(size_t)(hw0 + ty + i) * CC + c0 + tx] = tile[tx][ty + i];
}

// ---------------- helpers ----------------
__device__ __forceinline__ uint32_t s2u(const void* p) {
    uint32_t r;
    asm("{ .reg .u64 t; cvta.to.shared.u64 t, %1; cvt.u32.u64 %0, t; }" : "=r"(r) : "l"(p));
    return r;
}
__device__ __forceinline__ uint32_t sw128(uint32_t off) {
    return off ^ ((off >> 3) & 0x70);
}
__device__ __forceinline__ void ldsm_x4(uint32_t addr, uint32_t& r0, uint32_t& r1,
                                        uint32_t& r2, uint32_t& r3) {
    asm volatile("ldmatrix.sync.aligned.m8n8.x4.shared.b16 {%0,%1,%2,%3}, [%4];"
                 : "=r"(r0), "=r"(r1), "=r"(r2), "=r"(r3) : "r"(addr));
}
__device__ __forceinline__ void mma_fp16(float* d, const uint32_t* a, uint32_t b0, uint32_t b1) {
    asm volatile("mma.sync.aligned.m16n8k16.row.col.f32.f16.f16.f32 "
                 "{%0,%1,%2,%3}, {%4,%5,%6,%7}, {%8,%9}, {%0,%1,%2,%3};"
                 : "+f"(d[0]), "+f"(d[1]), "+f"(d[2]), "+f"(d[3])
                 : "r"(a[0]), "r"(a[1]), "r"(a[2]), "r"(a[3]), "r"(b0), "r"(b1));
}
__device__ __forceinline__ void cp16(uint32_t dst, const void* src) {
    asm volatile("cp.async.cg.shared.global [%0], [%1], 16;" :: "r"(dst), "l"(src) : "memory");
}
__device__ __forceinline__ void cp_commit() { asm volatile("cp.async.commit_group;" ::: "memory"); }
__device__ __forceinline__ void cp_wait0()  { asm volatile("cp.async.wait_group 0;"  ::: "memory"); }

extern __shared__ char smraw[];

__global__ __launch_bounds__(NT, 1)
void dcn_mma3_kernel(const float* __restrict__ offs,
                     const float* __restrict__ mask,
                     const float* __restrict__ bias,
                     float* __restrict__ out) {
    const int tid  = threadIdx.x;
    const int lane = tid & 31;
    const int wid  = tid >> 5;
    const int warpM = wid >> 2;        // 0..3 -> 64 o-rows
    const int warpN = wid & 3;         // 0..3 -> 32 px
    const int bb   = blockIdx.y;
    const int hw0  = blockIdx.x * TP;

    uint16_t* sI = (uint16_t*)(smraw + SM_SI);
    float*    sW = (float*)(smraw + SM_SW);
    const uint32_t uA = s2u(smraw + SM_A);
    const uint32_t uB = s2u(smraw + SM_B);

    // ---- taps: bilinear corner indices + mask-premultiplied weights ----
    for (int i = tid; i < KKT * TP; i += NT) {
        const int k  = i / TP;
        const int p  = i - k * TP;
        const int hw = hw0 + p;
        const int h  = hw >> 6;
        const int w  = hw & 63;

        const float oy = offs[((size_t)bb * 18 + k * 2 + 0) * HWSZ + hw];
        const float ox = offs[((size_t)bb * 18 + k * 2 + 1) * HWSZ + hw];
        const float m  = mask[((size_t)bb * KKT + k) * HWSZ + hw];

        const float py = (float)(h - 1 + k / 3) + oy;
        const float px = (float)(w - 1 + k % 3) + ox;
        const float fy = floorf(py), fx = floorf(px);
        const int y0 = (int)fy, x0 = (int)fx;
        const float ly = py - fy, lx = px - fx;
        const float hy = 1.0f - ly, hx = 1.0f - lx;

        const bool vy0 = (y0 >= 0) && (y0 < HH);
        const bool vy1 = (y0 + 1 >= 0) && (y0 + 1 < HH);
        const bool vx0 = (x0 >= 0) && (x0 < WWD);
        const bool vx1 = (x0 + 1 >= 0) && (x0 + 1 < WWD);
        const int cy0 = min(max(y0, 0), HH - 1);
        const int cy1 = min(max(y0 + 1, 0), HH - 1);
        const int cx0 = min(max(x0, 0), WWD - 1);
        const int cx1 = min(max(x0 + 1, 0), WWD - 1);

        sI[0 * 1152 + i] = (uint16_t)(cy0 * WWD + cx0);
        sI[1 * 1152 + i] = (uint16_t)(cy0 * WWD + cx1);
        sI[2 * 1152 + i] = (uint16_t)(cy1 * WWD + cx0);
        sI[3 * 1152 + i] = (uint16_t)(cy1 * WWD + cx1);
        sW[0 * 1152 + i] = (vy0 && vx0) ? hy * hx * m : 0.0f;
        sW[1 * 1152 + i] = (vy0 && vx1) ? hy * lx * m : 0.0f;
        sW[2 * 1152 + i] = (vy1 && vx0) ? ly * hx * m : 0.0f;
        sW[3 * 1152 + i] = (vy1 && vx1) ? ly * lx * m : 0.0f;
    }
    __syncthreads();

    const float* __restrict__ xb = g_xn + (size_t)bb * HWSZ * CC;

    float acc[4][4][4];
    #pragma unroll
    for (int mf = 0; mf < 4; ++mf)
        #pragma unroll
        for (int nf = 0; nf < 4; ++nf)
            #pragma unroll
            for (int r = 0; r < 4; ++r) acc[mf][nf][r] = 0.0f;

    // ---- stage A: 256 o x 128 c fp16 as two SW128 half-planes, via cp.async ----
    auto stageA = [&](int jt, int buf) {
        const int kpos = jt % KKT;
        const int c0   = (jt / KKT) * 128;
        const int q = tid & 7;          // 16B chunk within 128B row
        const int r = tid >> 3;         // 0..63
        const uint32_t abase = uA + buf * 65536;
        const uint32_t swoff = sw128((uint32_t)(r * 128 + q * 16));
        #pragma unroll
        for (int rr = 0; rr < 4; ++rr) {
            const int row = r + rr * 64;
            const __half* src = g_wh + ((size_t)kpos * OO + row) * CC + c0 + q * 8;
            cp16(abase + swoff + rr * 64 * 128, src);              // half-plane 0
            cp16(abase + 32768 + swoff + rr * 64 * 128, src + 64); // half-plane 1
        }
    };

    float4 g[2][4];           // gather regs: 2 px x 4 corners x 4 channels
    auto loadQ = [&](int jt, int q) {
        const int kpos = jt % KKT;
        const int c0   = (jt / KKT) * 128;
        const float* xc = xb + c0 + 4 * lane;
        #pragma unroll
        for (int e = 0; e < 2; ++e) {
            const int i = kpos * TP + wid * 8 + q * 2 + e;
            g[e][0] = *(const float4*)(xc + (size_t)sI[0 * 1152 + i] * CC);
            g[e][1] = *(const float4*)(xc + (size_t)sI[1 * 1152 + i] * CC);
            g[e][2] = *(const float4*)(xc + (size_t)sI[2 * 1152 + i] * CC);
            g[e][3] = *(const float4*)(xc + (size_t)sI[3 * 1152 + i] * CC);
        }
    };
    auto storeQ = [&](int jt, int q, int buf) {
        const int kpos = jt % KKT;
        const uint32_t bbase = uB + buf * 32768 + (lane >> 4) * 16384;
        #pragma unroll
        for (int e = 0; e < 2; ++e) {
            const int pp = wid * 8 + q * 2 + e;
            const int i  = kpos * TP + pp;
            const float w0 = sW[0 * 1152 + i], w1 = sW[1 * 1152 + i];
            const float w2 = sW[2 * 1152 + i], w3 = sW[3 * 1152 + i];
            float4 v;
            v.x = w0 * g[e][0].x + w1 * g[e][1].x + w2 * g[e][2].x + w3 * g[e][3].x;
            v.y = w0 * g[e][0].y + w1 * g[e][1].y + w2 * g[e][2].y + w3 * g[e][3].y;
            v.z = w0 * g[e][0].z + w1 * g[e][1].z + w2 * g[e][2].z + w3 * g[e][3].z;
            v.w = w0 * g[e][0].w + w1 * g[e][1].w + w2 * g[e][2].w + w3 * g[e][3].w;
            __half2 h01 = __float22half2_rn(make_float2(v.x, v.y));
            __half2 h23 = __float22half2_rn(make_float2(v.z, v.w));
            uint2 pk;
            pk.x = *(uint32_t*)&h01;
            pk.y = *(uint32_t*)&h23;
            const uint32_t sw = sw128((uint32_t)(pp * 128 + (lane & 15) * 8));
            *(uint2*)(smraw + (bbase - s2u(smraw)) + sw) = pk;
        }
    };
    auto mmaKS = [&](int ks, int buf) {
        const int half = ks >> 2;
        const int ksl  = ks & 3;
        const uint32_t abase = uA + buf * 65536 + half * 32768;
        const uint32_t bbase = uB + buf * 32768 + half * 16384;
        uint32_t a[4][4];
        #pragma unroll
        for (int mf = 0; mf < 4; ++mf) {
            const uint32_t off = (uint32_t)((warpM * 64 + mf * 16 + (lane & 15)) * 128
                                            + ksl * 32 + (lane >> 4) * 16);
            ldsm_x4(abase + sw128(off), a[mf][0], a[mf][1], a[mf][2], a[mf][3]);
        }
        uint32_t bfr[4][2];
        #pragma unroll
        for (int pb = 0; pb < 2; ++pb) {
            const uint32_t off = (uint32_t)((warpN * 32 + pb * 16 + (lane & 15)) * 128
                                            + ksl * 32 + (lane >> 4) * 16);
            uint32_t r0, r1, r2, r3;
            ldsm_x4(bbase + sw128(off), r0, r1, r2, r3);
            bfr[pb * 2 + 0][0] = r0; bfr[pb * 2 + 0][1] = r2;
            bfr[pb * 2 + 1][0] = r1; bfr[pb * 2 + 1][1] = r3;
        }
        #pragma unroll
        for (int mf = 0; mf < 4; ++mf)
            #pragma unroll
            for (int nf = 0; nf < 4; ++nf)
                mma_fp16(acc[mf][nf], a[mf], bfr[nf][0], bfr[nf][1]);
    };

    // ---- prologue: build iteration 0 into buffer 0 ----
    stageA(0, 0);
    cp_commit();
    #pragma unroll
    for (int q = 0; q < 4; ++q) { loadQ(0, q); storeQ(0, q, 0); }
    cp_wait0();
    __syncthreads();

    // ---- main loop: one sync per iter; build(it+1) woven into MMA(it) ----
    for (int it = 0; it < NITER; ++it) {
        const int buf = it & 1;
        const bool more = (it + 1 < NITER);
        if (more) { stageA(it + 1, buf ^ 1); cp_commit(); }

        if (more) loadQ(it + 1, 0);
        mmaKS(0, buf); mmaKS(1, buf);
        if (more) { storeQ(it + 1, 0, buf ^ 1); loadQ(it + 1, 1); }
        mmaKS(2, buf); mmaKS(3, buf);
        if (more) { storeQ(it + 1, 1, buf ^ 1); loadQ(it + 1, 2); }
        mmaKS(4, buf); mmaKS(5, buf);
        if (more) { storeQ(it + 1, 2, buf ^ 1); loadQ(it + 1, 3); }
        mmaKS(6, buf); mmaKS(7, buf);
        if (more) storeQ(it + 1, 3, buf ^ 1);

        cp_wait0();
        __syncthreads();
    }

    // ---- epilogue: bias add + fp32 stores ----
    #pragma unroll
    for (int mf = 0; mf < 4; ++mf) {
        const int o0 = warpM * 64 + mf * 16 + (lane >> 2);
        const float bv0 = bias[o0];
        const float bv1 = bias[o0 + 8];
        #pragma unroll
        for (int nf = 0; nf < 4; ++nf) {
            const int p = hw0 + warpN * 32 + nf * 8 + (lane & 3) * 2;
            float* d0 = out + ((size_t)(bb * OO + o0)) * HWSZ + p;
            float* d1 = out + ((size_t)(bb * OO + o0 + 8)) * HWSZ + p;
            float2 v0, v1;
            v0.x = acc[mf][nf][0] + bv0; v0.y = acc[mf][nf][1] + bv0;
            v1.x = acc[mf][nf][2] + bv1; v1.y = acc[mf][nf][3] + bv1;
            *(float2*)d0 = v0;
            *(float2*)d1 = v1;
        }
    }
}

extern "C" void kernel_launch(void* const* d_in, const int* in_sizes, int n_in,
                              void* d_out, int out_size) {
    const float* inp    = (const float*)d_in[0];  // [8,256,64,64]
    const float* offs   = (const float*)d_in[1];  // [8,18,64,64]
    const float* mask   = (const float*)d_in[2];  // [8,9,64,64]
    const float* weight = (const float*)d_in[3];  // [256,256,3,3]
    const float* bias   = (const float*)d_in[4];  // [256]
    float* out = (float*)d_out;                   // [8,256,64,64]

    cudaFuncSetAttribute(dcn_mma3_kernel,
                         cudaFuncAttributeMaxDynamicSharedMemorySize, SMEM_TOTAL);

    prep_weight<<<dim3(OO, KKT), CC>>>(weight);
    prep_nhwc<<<dim3(HWSZ / 32, CC / 32, BB), dim3(32, 8)>>>(inp);

    dim3 grid(HWSZ / TP, BB);   // (32, 8) = 256 CTAs
    dcn_mma3_kernel<<<grid, NT, SMEM_TOTAL>>>(offs, mask, bias, out);
}

// round 6
// speedup vs baseline: 8.6403x; 1.2779x over previous
#include <cuda_runtime.h>
#include <cuda_fp16.h>
#include <cstdint>

// Fixed problem shape
#define BB   8
#define CC   256
#define HH   64
#define WWD  64
#define OO   256
#define KKT  9
#define HWSZ 4096

#define TP   128         // pixel tile per CTA
#define NT   512         // 16 warps: 4 M-warps (o) x 4 N-warps (px)
#define NITER 18         // 2 c-chunks of 128 x 9 kpos

// ---- smem layout (bytes) ----
#define SM_SI   0
#define SM_SW   9216
#define SM_A    27648       // 2 bufs x 65536 (256 o x 128 c fp16, two SW128 half-planes)
#define SM_B    158720      // 2 bufs x 32768 (128 px x 128 c fp16, two SW128 half-planes)
#define SMEM_TOTAL 224256

// ---- device scratch ----
__device__ __align__(16) __half g_wh[KKT * OO * CC];              // [k][o][c] fp16
__device__ __align__(16) __half g_xn[(size_t)BB * HWSZ * CC];     // NHWC fp16

// ---------------- prep kernels ----------------
__global__ void prep_weight(const float* __restrict__ w) {
    int o = blockIdx.x, k = blockIdx.y, c = threadIdx.x;
    float v = w[((size_t)o * CC + c) * KKT + k];
    g_wh[((size_t)k * OO + o) * CC + c] = __float2half_rn(v);
}

__global__ void prep_nhwc(const float* __restrict__ x) {
    __shared__ float tile[32][33];
    int bb = blockIdx.z, hw0 = blockIdx.x * 32, c0 = blockIdx.y * 32;
    int tx = threadIdx.x, ty = threadIdx.y;
    const float* src = x + (size_t)bb * CC * HWSZ;
    #pragma unroll
    for (int i = 0; i < 32; i += 8)
        tile[ty + i][tx] = src[(size_t)(c0 + ty + i) * HWSZ + hw0 + tx];
    __syncthreads();
    __half* dst = g_xn + (size_t)bb * HWSZ * CC;
    #pragma unroll
    for (int i = 0; i < 32; i += 8)
        dst[(size_t)(hw0 + ty + i) * CC + c0 + tx] = __float2half_rn(tile[tx][ty + i]);
}

// ---------------- helpers ----------------
__device__ __forceinline__ uint32_t s2u(const void* p) {
    uint32_t r;
    asm("{ .reg .u64 t; cvta.to.shared.u64 t, %1; cvt.u32.u64 %0, t; }" : "=r"(r) : "l"(p));
    return r;
}
__device__ __forceinline__ uint32_t sw128(uint32_t off) {
    return off ^ ((off >> 3) & 0x70);
}
__device__ __forceinline__ void ldsm_x4(uint32_t addr, uint32_t& r0, uint32_t& r1,
                                        uint32_t& r2, uint32_t& r3) {
    asm volatile("ldmatrix.sync.aligned.m8n8.x4.shared.b16 {%0,%1,%2,%3}, [%4];"
                 : "=r"(r0), "=r"(r1), "=r"(r2), "=r"(r3) : "r"(addr));
}
__device__ __forceinline__ void mma_fp16(float* d, const uint32_t* a, uint32_t b0, uint32_t b1) {
    asm volatile("mma.sync.aligned.m16n8k16.row.col.f32.f16.f16.f32 "
                 "{%0,%1,%2,%3}, {%4,%5,%6,%7}, {%8,%9}, {%0,%1,%2,%3};"
                 : "+f"(d[0]), "+f"(d[1]), "+f"(d[2]), "+f"(d[3])
                 : "r"(a[0]), "r"(a[1]), "r"(a[2]), "r"(a[3]), "r"(b0), "r"(b1));
}
__device__ __forceinline__ void cp16(uint32_t dst, const void* src) {
    asm volatile("cp.async.cg.shared.global [%0], [%1], 16;" :: "r"(dst), "l"(src) : "memory");
}
__device__ __forceinline__ void cp_commit() { asm volatile("cp.async.commit_group;" ::: "memory"); }
__device__ __forceinline__ void cp_wait0()  { asm volatile("cp.async.wait_group 0;"  ::: "memory"); }

extern __shared__ char smraw[];

__global__ __launch_bounds__(NT, 1)
void dcn_mma4_kernel(const float* __restrict__ offs,
                     const float* __restrict__ mask,
                     const float* __restrict__ bias,
                     float* __restrict__ out) {
    const int tid  = threadIdx.x;
    const int lane = tid & 31;
    const int wid  = tid >> 5;
    const int warpM = wid >> 2;        // 0..3 -> 64 o-rows
    const int warpN = wid & 3;         // 0..3 -> 32 px
    const int bb   = blockIdx.y;
    const int hw0  = blockIdx.x * TP;

    uint16_t* sI = (uint16_t*)(smraw + SM_SI);
    float*    sW = (float*)(smraw + SM_SW);
    const uint32_t uA = s2u(smraw + SM_A);
    const uint32_t uB = s2u(smraw + SM_B);

    // ---- taps: bilinear corner indices + mask-premultiplied weights ----
    for (int i = tid; i < KKT * TP; i += NT) {
        const int k  = i / TP;
        const int p  = i - k * TP;
        const int hw = hw0 + p;
        const int h  = hw >> 6;
        const int w  = hw & 63;

        const float oy = offs[((size_t)bb * 18 + k * 2 + 0) * HWSZ + hw];
        const float ox = offs[((size_t)bb * 18 + k * 2 + 1) * HWSZ + hw];
        const float m  = mask[((size_t)bb * KKT + k) * HWSZ + hw];

        const float py = (float)(h - 1 + k / 3) + oy;
        const float px = (float)(w - 1 + k % 3) + ox;
        const float fy = floorf(py), fx = floorf(px);
        const int y0 = (int)fy, x0 = (int)fx;
        const float ly = py - fy, lx = px - fx;
        const float hy = 1.0f - ly, hx = 1.0f - lx;

        const bool vy0 = (y0 >= 0) && (y0 < HH);
        const bool vy1 = (y0 + 1 >= 0) && (y0 + 1 < HH);
        const bool vx0 = (x0 >= 0) && (x0 < WWD);
        const bool vx1 = (x0 + 1 >= 0) && (x0 + 1 < WWD);
        const int cy0 = min(max(y0, 0), HH - 1);
        const int cy1 = min(max(y0 + 1, 0), HH - 1);
        const int cx0 = min(max(x0, 0), WWD - 1);
        const int cx1 = min(max(x0 + 1, 0), WWD - 1);

        sI[0 * 1152 + i] = (uint16_t)(cy0 * WWD + cx0);
        sI[1 * 1152 + i] = (uint16_t)(cy0 * WWD + cx1);
        sI[2 * 1152 + i] = (uint16_t)(cy1 * WWD + cx0);
        sI[3 * 1152 + i] = (uint16_t)(cy1 * WWD + cx1);
        sW[0 * 1152 + i] = (vy0 && vx0) ? hy * hx * m : 0.0f;
        sW[1 * 1152 + i] = (vy0 && vx1) ? hy * lx * m : 0.0f;
        sW[2 * 1152 + i] = (vy1 && vx0) ? ly * hx * m : 0.0f;
        sW[3 * 1152 + i] = (vy1 && vx1) ? ly * lx * m : 0.0f;
    }
    __syncthreads();

    const __half* __restrict__ xb = g_xn + (size_t)bb * HWSZ * CC;

    float acc[4][4][4];
    #pragma unroll
    for (int mf = 0; mf < 4; ++mf)
        #pragma unroll
        for (int nf = 0; nf < 4; ++nf)
            #pragma unroll
            for (int r = 0; r < 4; ++r) acc[mf][nf][r] = 0.0f;

    // ---- stage A: 256 o x 128 c fp16 as two SW128 half-planes, via cp.async ----
    auto stageA = [&](int jt, int buf) {
        const int kpos = jt % KKT;
        const int c0   = (jt / KKT) * 128;
        const int q = tid & 7;          // 16B chunk within 128B row
        const int r = tid >> 3;         // 0..63
        const uint32_t abase = uA + buf * 65536;
        const uint32_t swoff = sw128((uint32_t)(r * 128 + q * 16));
        #pragma unroll
        for (int rr = 0; rr < 4; ++rr) {
            const int row = r + rr * 64;
            const __half* src = g_wh + ((size_t)kpos * OO + row) * CC + c0 + q * 8;
            cp16(abase + swoff + rr * 64 * 128, src);              // half-plane 0
            cp16(abase + 32768 + swoff + rr * 64 * 128, src + 64); // half-plane 1
        }
    };

    uint2 g[2][4];            // gather regs: 2 px x 4 corners x 4 fp16 channels
    auto loadQ = [&](int jt, int q) {
        const int kpos = jt % KKT;
        const int c0   = (jt / KKT) * 128;
        const __half* xc = xb + c0 + 4 * lane;
        #pragma unroll
        for (int e = 0; e < 2; ++e) {
            const int i = kpos * TP + wid * 8 + q * 2 + e;
            g[e][0] = *(const uint2*)(xc + (size_t)sI[0 * 1152 + i] * CC);
            g[e][1] = *(const uint2*)(xc + (size_t)sI[1 * 1152 + i] * CC);
            g[e][2] = *(const uint2*)(xc + (size_t)sI[2 * 1152 + i] * CC);
            g[e][3] = *(const uint2*)(xc + (size_t)sI[3 * 1152 + i] * CC);
        }
    };
    auto storeQ = [&](int jt, int q, int buf) {
        const int kpos = jt % KKT;
        const uint32_t bbase = uB + buf * 32768 + (lane >> 4) * 16384;
        #pragma unroll
        for (int e = 0; e < 2; ++e) {
            const int pp = wid * 8 + q * 2 + e;
            const int i  = kpos * TP + pp;
            const float w0 = sW[0 * 1152 + i], w1 = sW[1 * 1152 + i];
            const float w2 = sW[2 * 1152 + i], w3 = sW[3 * 1152 + i];
            float2 c0a = __half22float2(*(__half2*)&g[e][0].x);
            float2 c0b = __half22float2(*(__half2*)&g[e][0].y);
            float2 c1a = __half22float2(*(__half2*)&g[e][1].x);
            float2 c1b = __half22float2(*(__half2*)&g[e][1].y);
            float2 c2a = __half22float2(*(__half2*)&g[e][2].x);
            float2 c2b = __half22float2(*(__half2*)&g[e][2].y);
            float2 c3a = __half22float2(*(__half2*)&g[e][3].x);
            float2 c3b = __half22float2(*(__half2*)&g[e][3].y);
            float2 va, vb;
            va.x = w0 * c0a.x + w1 * c1a.x + w2 * c2a.x + w3 * c3a.x;
            va.y = w0 * c0a.y + w1 * c1a.y + w2 * c2a.y + w3 * c3a.y;
            vb.x = w0 * c0b.x + w1 * c1b.x + w2 * c2b.x + w3 * c3b.x;
            vb.y = w0 * c0b.y + w1 * c1b.y + w2 * c2b.y + w3 * c3b.y;
            __half2 h01 = __float22half2_rn(va);
            __half2 h23 = __float22half2_rn(vb);
            uint2 pk;
            pk.x = *(uint32_t*)&h01;
            pk.y = *(uint32_t*)&h23;
            const uint32_t sw = sw128((uint32_t)(pp * 128 + (lane & 15) * 8));
            *(uint2*)(smraw + (bbase - s2u(smraw)) + sw) = pk;
        }
    };
    auto mmaKS = [&](int ks, int buf) {
        const int half = ks >> 2;
        const int ksl  = ks & 3;
        const uint32_t abase = uA + buf * 65536 + half * 32768;
        const uint32_t bbase = uB + buf * 32768 + half * 16384;
        uint32_t a[4][4];
        #pragma unroll
        for (int mf = 0; mf < 4; ++mf) {
            const uint32_t off = (uint32_t)((warpM * 64 + mf * 16 + (lane & 15)) * 128
                                            + ksl * 32 + (lane >> 4) * 16);
            ldsm_x4(abase + sw128(off), a[mf][0], a[mf][1], a[mf][2], a[mf][3]);
        }
        uint32_t bfr[4][2];
        #pragma unroll
        for (int pb = 0; pb < 2; ++pb) {
            const uint32_t off = (uint32_t)((warpN * 32 + pb * 16 + (lane & 15)) * 128
                                            + ksl * 32 + (lane >> 4) * 16);
            uint32_t r0, r1, r2, r3;
            ldsm_x4(bbase + sw128(off), r0, r1, r2, r3);
            bfr[pb * 2 + 0][0] = r0; bfr[pb * 2 + 0][1] = r2;
            bfr[pb * 2 + 1][0] = r1; bfr[pb * 2 + 1][1] = r3;
        }
        #pragma unroll
        for (int mf = 0; mf < 4; ++mf)
            #pragma unroll
            for (int nf = 0; nf < 4; ++nf)
                mma_fp16(acc[mf][nf], a[mf], bfr[nf][0], bfr[nf][1]);
    };

    // ---- prologue: build iteration 0 into buffer 0 ----
    stageA(0, 0);
    cp_commit();
    #pragma unroll
    for (int q = 0; q < 4; ++q) { loadQ(0, q); storeQ(0, q, 0); }
    cp_wait0();
    __syncthreads();

    // ---- main loop: one sync per iter; build(it+1) woven into MMA(it) ----
    for (int it = 0; it < NITER; ++it) {
        const int buf = it & 1;
        const bool more = (it + 1 < NITER);
        if (more) { stageA(it + 1, buf ^ 1); cp_commit(); }

        if (more) loadQ(it + 1, 0);
        mmaKS(0, buf); mmaKS(1, buf);
        if (more) { storeQ(it + 1, 0, buf ^ 1); loadQ(it + 1, 1); }
        mmaKS(2, buf); mmaKS(3, buf);
        if (more) { storeQ(it + 1, 1, buf ^ 1); loadQ(it + 1, 2); }
        mmaKS(4, buf); mmaKS(5, buf);
        if (more) { storeQ(it + 1, 2, buf ^ 1); loadQ(it + 1, 3); }
        mmaKS(6, buf); mmaKS(7, buf);
        if (more) storeQ(it + 1, 3, buf ^ 1);

        cp_wait0();
        __syncthreads();
    }

    // ---- epilogue: bias add + fp32 stores ----
    #pragma unroll
    for (int mf = 0; mf < 4; ++mf) {
        const int o0 = warpM * 64 + mf * 16 + (lane >> 2);
        const float bv0 = bias[o0];
        const float bv1 = bias[o0 + 8];
        #pragma unroll
        for (int nf = 0; nf < 4; ++nf) {
            const int p = hw0 + warpN * 32 + nf * 8 + (lane & 3) * 2;
            float* d0 = out + ((size_t)(bb * OO + o0)) * HWSZ + p;
            float* d1 = out + ((size_t)(bb * OO + o0 + 8)) * HWSZ + p;
            float2 v0, v1;
            v0.x = acc[mf][nf][0] + bv0; v0.y = acc[mf][nf][1] + bv0;
            v1.x = acc[mf][nf][2] + bv1; v1.y = acc[mf][nf][3] + bv1;
            *(float2*)d0 = v0;
            *(float2*)d1 = v1;
        }
    }
}

extern "C" void kernel_launch(void* const* d_in, const int* in_sizes, int n_in,
                              void* d_out, int out_size) {
    const float* inp    = (const float*)d_in[0];  // [8,256,64,64]
    const float* offs   = (const float*)d_in[1];  // [8,18,64,64]
    const float* mask   = (const float*)d_in[2];  // [8,9,64,64]
    const float* weight = (const float*)d_in[3];  // [256,256,3,3]
    const float* bias   = (const float*)d_in[4];  // [256]
    float* out = (float*)d_out;                   // [8,256,64,64]

    cudaFuncSetAttribute(dcn_mma4_kernel,
                         cudaFuncAttributeMaxDynamicSharedMemorySize, SMEM_TOTAL);

    prep_weight<<<dim3(OO, KKT), CC>>>(weight);
    prep_nhwc<<<dim3(HWSZ / 32, CC / 32, BB), dim3(32, 8)>>>(inp);

    dim3 grid(HWSZ / TP, BB);   // (32, 8) = 256 CTAs
    dcn_mma4_kernel<<<grid, NT, SMEM_TOTAL>>>(offs, mask, bias, out);
}